// round 1
// baseline (speedup 1.0000x reference)
#include <cuda_runtime.h>
#include <math.h>

#define NUM_MOLS 1024
#define N_ATOMS  32
#define ZD       64
#define HID      256
#define NAT      10
#define NBT      5
#define EPM      496                       // C(32,2) edges per molecule
#define TOTAL_ATOMS (NUM_MOLS * N_ATOMS)   // 32768
#define TOTAL_EDGES (NUM_MOLS * EPM)       // 507904
#define ROWS_PER_BLK 128
#define NBLK_G1 (TOTAL_ATOMS / ROWS_PER_BLK)  // 256
#define ZP 68                              // padded smem row stride (floats), 16B aligned

// ---------------- scratch (device globals: no allocations allowed) ----------
__device__ float g_h[TOTAL_ATOMS * HID];       // 32 MB hidden activations
__device__ float g_psum[NBLK_G1 * HID];        // BN partial sums
__device__ float g_psq[NBLK_G1 * HID];         // BN partial sums of squares
__device__ float g_scale[HID];                 // BN folded scale
__device__ float g_shift[HID];                 // BN folded shift
__device__ float g_Ws[NBT * ZD * ZD];          // symmetrized bond matrices

__device__ __forceinline__ float gelu_exact(float x) {
    return 0.5f * x * (1.0f + erff(x * 0.70710678118654752f));
}

// ---------------- 0) symmetrize bond matrices -------------------------------
__global__ void sym_kernel(const float* __restrict__ B) {
    int idx = blockIdx.x * blockDim.x + threadIdx.x;   // 5*64*64 = 20480
    if (idx >= NBT * ZD * ZD) return;
    int t = idx >> 12;
    int d = (idx >> 6) & 63;
    int c = idx & 63;
    g_Ws[idx] = 0.5f * (B[t * ZD * ZD + d * ZD + c] + B[t * ZD * ZD + c * ZD + d]);
}

// ---------------- 1) h = z @ W1 + b1, plus BN partials ----------------------
// Block: 128 rows x 256 cols. Thread owns one output column; W1 column in regs.
__global__ void __launch_bounds__(256) gemm1_kernel(
    const float* __restrict__ z, const float* __restrict__ W1,
    const float* __restrict__ b1) {
    __shared__ float zs[ROWS_PER_BLK * ZD];   // 32 KB
    const int c  = threadIdx.x;
    const int r0 = blockIdx.x * ROWS_PER_BLK;

    // cooperative float4 load of the z tile (fully coalesced)
    {
        const float4* src = (const float4*)(z + (size_t)r0 * ZD);
        float4* dst = (float4*)zs;
        #pragma unroll
        for (int i = 0; i < (ROWS_PER_BLK * ZD / 4) / 256; i++)
            dst[c + i * 256] = src[c + i * 256];
    }
    float w[ZD];
    #pragma unroll
    for (int d = 0; d < ZD; d++) w[d] = W1[d * HID + c];
    const float bc = b1[c];
    __syncthreads();

    float s = 0.f, sq = 0.f;
    for (int r = 0; r < ROWS_PER_BLK; r++) {
        float acc = bc;
        const float4* zr = (const float4*)(zs + r * ZD);
        #pragma unroll
        for (int d4 = 0; d4 < 16; d4++) {
            float4 v = zr[d4];             // smem broadcast (same addr across warp)
            acc += v.x * w[d4 * 4 + 0];
            acc += v.y * w[d4 * 4 + 1];
            acc += v.z * w[d4 * 4 + 2];
            acc += v.w * w[d4 * 4 + 3];
        }
        g_h[(size_t)(r0 + r) * HID + c] = acc;
        s  += acc;
        sq += acc * acc;
    }
    g_psum[blockIdx.x * HID + c] = s;
    g_psq [blockIdx.x * HID + c] = sq;
}

// ---------------- 2) finalize BN stats (deterministic tree reduction) -------
__global__ void bnfin_kernel(const float* __restrict__ gamma,
                             const float* __restrict__ beta) {
    const int c = blockIdx.x;   // one block per hidden column
    const int t = threadIdx.x;  // 256 threads, one per partial
    __shared__ float ss[256], sqs[256];
    ss[t]  = g_psum[t * HID + c];
    sqs[t] = g_psq [t * HID + c];
    __syncthreads();
    #pragma unroll
    for (int o = 128; o > 0; o >>= 1) {
        if (t < o) { ss[t] += ss[t + o]; sqs[t] += sqs[t + o]; }
        __syncthreads();
    }
    if (t == 0) {
        const float invN = 1.0f / (float)TOTAL_ATOMS;
        float mean = ss[0] * invN;
        float var  = sqs[0] * invN - mean * mean;
        float inv  = rsqrtf(var + 1e-5f);
        float sc   = inv * gamma[c];
        g_scale[c] = sc;
        g_shift[c] = beta[c] - mean * sc;
    }
}

// ---------------- 3) atom_types = gelu(bn(h)) @ W2 + b2 ---------------------
__global__ void __launch_bounds__(256) atom_kernel(
    const float* __restrict__ W2, const float* __restrict__ b2,
    float* __restrict__ out) {
    __shared__ float w2s[HID * NAT];   // 10 KB
    __shared__ float scs[HID], shs[HID];
    const int tid = threadIdx.x;
    for (int i = tid; i < HID * NAT; i += 256) w2s[i] = W2[i];
    scs[tid] = g_scale[tid];
    shs[tid] = g_shift[tid];
    __syncthreads();

    const int row = blockIdx.x * 256 + tid;
    float acc[NAT];
    #pragma unroll
    for (int j = 0; j < NAT; j++) acc[j] = b2[j];

    const float4* hr = (const float4*)(g_h + (size_t)row * HID);
    #pragma unroll 4
    for (int k4 = 0; k4 < HID / 4; k4++) {
        float4 v = hr[k4];
        int k = k4 * 4;
        float g0 = gelu_exact(v.x * scs[k + 0] + shs[k + 0]);
        float g1 = gelu_exact(v.y * scs[k + 1] + shs[k + 1]);
        float g2 = gelu_exact(v.z * scs[k + 2] + shs[k + 2]);
        float g3 = gelu_exact(v.w * scs[k + 3] + shs[k + 3]);
        #pragma unroll
        for (int j = 0; j < NAT; j++) {
            acc[j] += g0 * w2s[(k + 0) * NAT + j];
            acc[j] += g1 * w2s[(k + 1) * NAT + j];
            acc[j] += g2 * w2s[(k + 2) * NAT + j];
            acc[j] += g3 * w2s[(k + 3) * NAT + j];
        }
    }
    #pragma unroll
    for (int j = 0; j < NAT; j++) out[(size_t)row * NAT + j] = acc[j];
}

// ---------------- 4) edge logits, per-molecule restructured GEMM ------------
// Per mol m, per type t:  U = Z_m @ Ws_t (32x64), logit(i,j) = U[i] . Z_m[j].
// Writes RAW logits; softmax done by a follow-up kernel.
__global__ void __launch_bounds__(256) edge_kernel(
    const float* __restrict__ z, float* __restrict__ out) {
    __shared__ float zs[N_ATOMS * ZP];   // 8.5 KB (padded, 16B-aligned rows)
    __shared__ float us[N_ATOMS * ZP];   // 8.5 KB
    const int tid = threadIdx.x;
    const int mol = blockIdx.x;

    const float* zm = z + (size_t)mol * N_ATOMS * ZD;
    for (int idx = tid; idx < N_ATOMS * ZD; idx += 256)
        zs[(idx >> 6) * ZP + (idx & 63)] = zm[idx];

    // my edges: e1 = tid, e2 = tid + 256 (if < 496)
    int i1, j1, i2 = 0, j2 = 0;
    { int i = 0, rem = tid;       while (rem >= 31 - i) { rem -= 31 - i; i++; } i1 = i; j1 = i + 1 + rem; }
    const bool has2 = (tid + 256) < EPM;
    if (has2) { int i = 0, rem = tid + 256; while (rem >= 31 - i) { rem -= 31 - i; i++; } i2 = i; j2 = i + 1 + rem; }

    const int c  = tid & 63;       // U column owned by this thread
    const int ib = tid >> 6;       // base row (4 rows/pass, 8 passes)
    float* eout = out + (size_t)TOTAL_ATOMS * NAT;
    const size_t base1 = ((size_t)mol * EPM + tid) * NBT;
    const size_t base2 = ((size_t)mol * EPM + tid + 256) * NBT;

    __syncthreads();

    for (int t = 0; t < NBT; t++) {
        const float* __restrict__ W = g_Ws + t * ZD * ZD;
        // U = Z @ W  (coalesced W reads across c; zs broadcast within warp)
        #pragma unroll
        for (int p = 0; p < 8; p++) {
            const int i = ib + p * 4;
            float acc = 0.f;
            const float4* zr = (const float4*)(zs + i * ZP);
            #pragma unroll 4
            for (int d4 = 0; d4 < 16; d4++) {
                float4 v = zr[d4];
                int d = d4 * 4;
                acc += v.x * W[(d + 0) * ZD + c];
                acc += v.y * W[(d + 1) * ZD + c];
                acc += v.z * W[(d + 2) * ZD + c];
                acc += v.w * W[(d + 3) * ZD + c];
            }
            us[i * ZP + c] = acc;
        }
        __syncthreads();

        // logit(e) = U[i] . Z[j]
        {
            const float4* u = (const float4*)(us + i1 * ZP);
            const float4* v = (const float4*)(zs + j1 * ZP);
            float a = 0.f;
            #pragma unroll 8
            for (int d4 = 0; d4 < 16; d4++) {
                float4 uu = u[d4]; float4 vv = v[d4];
                a += uu.x * vv.x + uu.y * vv.y + uu.z * vv.z + uu.w * vv.w;
            }
            eout[base1 + t] = a;
        }
        if (has2) {
            const float4* u = (const float4*)(us + i2 * ZP);
            const float4* v = (const float4*)(zs + j2 * ZP);
            float a = 0.f;
            #pragma unroll 8
            for (int d4 = 0; d4 < 16; d4++) {
                float4 uu = u[d4]; float4 vv = v[d4];
                a += uu.x * vv.x + uu.y * vv.y + uu.z * vv.z + uu.w * vv.w;
            }
            eout[base2 + t] = a;
        }
        __syncthreads();
    }
}

// ---------------- 5) in-place softmax over the 5 bond types -----------------
__global__ void softmax_kernel(float* __restrict__ out) {
    const size_t e = (size_t)blockIdx.x * blockDim.x + threadIdx.x;
    if (e >= TOTAL_EDGES) return;
    float* p = out + (size_t)TOTAL_ATOMS * NAT + e * NBT;
    float l0 = p[0], l1 = p[1], l2 = p[2], l3 = p[3], l4 = p[4];
    float m = fmaxf(fmaxf(fmaxf(l0, l1), fmaxf(l2, l3)), l4);
    float e0 = __expf(l0 - m), e1 = __expf(l1 - m), e2 = __expf(l2 - m),
          e3 = __expf(l3 - m), e4 = __expf(l4 - m);
    float inv = 1.0f / (e0 + e1 + e2 + e3 + e4);
    p[0] = e0 * inv; p[1] = e1 * inv; p[2] = e2 * inv; p[3] = e3 * inv; p[4] = e4 * inv;
}

// ---------------- launch ----------------------------------------------------
extern "C" void kernel_launch(void* const* d_in, const int* in_sizes, int n_in,
                              void* d_out, int out_size) {
    const float* z     = (const float*)d_in[0];
    const float* W1    = (const float*)d_in[1];
    const float* b1    = (const float*)d_in[2];
    const float* gamma = (const float*)d_in[3];
    const float* beta  = (const float*)d_in[4];
    const float* W2    = (const float*)d_in[5];
    const float* b2    = (const float*)d_in[6];
    const float* bond  = (const float*)d_in[7];
    // d_in[8] = edge_index: structure is deterministic (all i<j pairs per mol,
    // mol-major, lexicographic) so we regenerate indices on-device.
    float* out = (float*)d_out;

    sym_kernel     <<<(NBT * ZD * ZD + 255) / 256, 256>>>(bond);
    gemm1_kernel   <<<NBLK_G1, 256>>>(z, W1, b1);
    bnfin_kernel   <<<HID, 256>>>(gamma, beta);
    atom_kernel    <<<TOTAL_ATOMS / 256, 256>>>(W2, b2, out);
    edge_kernel    <<<NUM_MOLS, 256>>>(z, out);
    softmax_kernel <<<(TOTAL_EDGES + 255) / 256, 256>>>(out);
}

// round 2
// speedup vs baseline: 1.0012x; 1.0012x over previous
#include <cuda_runtime.h>
#include <math.h>

#define NUM_MOLS 1024
#define N_ATOMS  32
#define ZD       64
#define HID      256
#define NAT      10
#define NBT      5
#define EPM      496
#define TOTAL_ATOMS (NUM_MOLS * N_ATOMS)   // 32768
#define TOTAL_EDGES (NUM_MOLS * EPM)       // 507904
#define ROWS_PER_BLK 128
#define NBLK_G1 (TOTAL_ATOMS / ROWS_PER_BLK)  // 256
#define ZP 68

// ---------------- scratch (device globals) ----------------------------------
__device__ float g_h[TOTAL_ATOMS * HID];
__device__ float g_psum[NBLK_G1 * HID];
__device__ float g_psq[NBLK_G1 * HID];
__device__ float g_scale[HID];
__device__ float g_shift[HID];
__device__ float g_Ws[NBT * ZD * ZD];

__device__ __forceinline__ float gelu_exact(float x) {
    return 0.5f * x * (1.0f + erff(x * 0.70710678118654752f));
}

// ---------------- 0) symmetrize bond matrices -------------------------------
__global__ void sym_kernel(const float* __restrict__ B) {
    int idx = blockIdx.x * blockDim.x + threadIdx.x;
    if (idx >= NBT * ZD * ZD) return;
    int t = idx >> 12;
    int d = (idx >> 6) & 63;
    int c = idx & 63;
    g_Ws[idx] = 0.5f * (B[t * ZD * ZD + d * ZD + c] + B[t * ZD * ZD + c * ZD + d]);
}

// ---------------- 1) h = z @ W1 + b1, plus BN partials ----------------------
__global__ void __launch_bounds__(256) gemm1_kernel(
    const float* __restrict__ z, const float* __restrict__ W1,
    const float* __restrict__ b1) {
    __shared__ float zs[ROWS_PER_BLK * ZD];
    const int c  = threadIdx.x;
    const int r0 = blockIdx.x * ROWS_PER_BLK;
    {
        const float4* src = (const float4*)(z + (size_t)r0 * ZD);
        float4* dst = (float4*)zs;
        #pragma unroll
        for (int i = 0; i < (ROWS_PER_BLK * ZD / 4) / 256; i++)
            dst[c + i * 256] = src[c + i * 256];
    }
    float w[ZD];
    #pragma unroll
    for (int d = 0; d < ZD; d++) w[d] = W1[d * HID + c];
    const float bc = b1[c];
    __syncthreads();

    float s = 0.f, sq = 0.f;
    for (int r = 0; r < ROWS_PER_BLK; r++) {
        float a0 = 0.f, a1 = 0.f;   // dual accumulators: break the dep chain
        const float4* zr = (const float4*)(zs + r * ZD);
        #pragma unroll
        for (int d4 = 0; d4 < 16; d4 += 2) {
            float4 v0 = zr[d4], v1 = zr[d4 + 1];
            a0 += v0.x * w[d4*4+0] + v0.y * w[d4*4+1] + v0.z * w[d4*4+2] + v0.w * w[d4*4+3];
            a1 += v1.x * w[d4*4+4] + v1.y * w[d4*4+5] + v1.z * w[d4*4+6] + v1.w * w[d4*4+7];
        }
        float acc = bc + a0 + a1;
        g_h[(size_t)(r0 + r) * HID + c] = acc;
        s  += acc;
        sq += acc * acc;
    }
    g_psum[blockIdx.x * HID + c] = s;
    g_psq [blockIdx.x * HID + c] = sq;
}

// ---------------- 2) finalize BN stats --------------------------------------
__global__ void bnfin_kernel(const float* __restrict__ gamma,
                             const float* __restrict__ beta) {
    const int c = blockIdx.x;
    const int t = threadIdx.x;
    __shared__ float ss[256], sqs[256];
    ss[t]  = g_psum[t * HID + c];
    sqs[t] = g_psq [t * HID + c];
    __syncthreads();
    #pragma unroll
    for (int o = 128; o > 0; o >>= 1) {
        if (t < o) { ss[t] += ss[t + o]; sqs[t] += sqs[t + o]; }
        __syncthreads();
    }
    if (t == 0) {
        const float invN = 1.0f / (float)TOTAL_ATOMS;
        float mean = ss[0] * invN;
        float var  = sqs[0] * invN - mean * mean;
        float inv  = rsqrtf(var + 1e-5f);
        float sc   = inv * gamma[c];
        g_scale[c] = sc;
        g_shift[c] = beta[c] - mean * sc;
    }
}

// ---------------- 3) atom_types: warp-per-row, coalesced --------------------
#define ATOM_BLKS 512
__global__ void __launch_bounds__(256) atom_kernel(
    const float* __restrict__ W2, const float* __restrict__ b2,
    float* __restrict__ out) {
    __shared__ float w2t[NAT * HID];          // transposed: [j][k]
    __shared__ float scs[HID], shs[HID];
    const int tid  = threadIdx.x;
    const int lane = tid & 31;
    const int wrp  = tid >> 5;
    for (int i = tid; i < NAT * HID; i += 256) {
        int j = i >> 8, k = i & 255;
        w2t[i] = W2[k * NAT + j];
    }
    scs[tid] = g_scale[tid];
    shs[tid] = g_shift[tid];
    __syncthreads();

    const float bj = (lane < NAT) ? b2[lane] : 0.f;
    const int k0 = lane * 4, k1 = 128 + lane * 4;
    const float4 sc0 = *(const float4*)(scs + k0);
    const float4 sc1 = *(const float4*)(scs + k1);
    const float4 sh0 = *(const float4*)(shs + k0);
    const float4 sh1 = *(const float4*)(shs + k1);

    const int nwarps = ATOM_BLKS * 8;
    for (int row = blockIdx.x * 8 + wrp; row < TOTAL_ATOMS; row += nwarps) {
        const float4* hr = (const float4*)(g_h + (size_t)row * HID);
        float4 a = hr[lane];        // coalesced 512B across warp
        float4 b = hr[32 + lane];
        float g0 = gelu_exact(a.x * sc0.x + sh0.x);
        float g1 = gelu_exact(a.y * sc0.y + sh0.y);
        float g2 = gelu_exact(a.z * sc0.z + sh0.z);
        float g3 = gelu_exact(a.w * sc0.w + sh0.w);
        float g4 = gelu_exact(b.x * sc1.x + sh1.x);
        float g5 = gelu_exact(b.y * sc1.y + sh1.y);
        float g6 = gelu_exact(b.z * sc1.z + sh1.z);
        float g7 = gelu_exact(b.w * sc1.w + sh1.w);

        float acc[NAT];
        #pragma unroll
        for (int j = 0; j < NAT; j++) {
            float4 w0 = *(const float4*)(w2t + j * HID + k0);
            float4 w1 = *(const float4*)(w2t + j * HID + k1);
            acc[j] = g0 * w0.x + g1 * w0.y + g2 * w0.z + g3 * w0.w
                   + g4 * w1.x + g5 * w1.y + g6 * w1.z + g7 * w1.w;
        }
        #pragma unroll
        for (int o = 16; o > 0; o >>= 1)
            #pragma unroll
            for (int j = 0; j < NAT; j++)
                acc[j] += __shfl_xor_sync(0xffffffffu, acc[j], o);
        float v = 0.f;
        #pragma unroll
        for (int j = 0; j < NAT; j++) if (lane == j) v = acc[j];
        if (lane < NAT) out[(size_t)row * NAT + lane] = v + bj;
    }
}

// ---------------- 4) edge logits + fused softmax ----------------------------
// W_sym is symmetric: column c == row c -> W column lives in registers,
// loaded with 16 contiguous LDG.128 per type (no scalar-LDG storm).
__global__ void __launch_bounds__(256, 2) edge_kernel(
    const float* __restrict__ z, float* __restrict__ out) {
    __shared__ float zs[N_ATOMS * ZP];
    __shared__ float us[N_ATOMS * ZP];
    const int tid = threadIdx.x;
    const int mol = blockIdx.x;

    const float* zm = z + (size_t)mol * N_ATOMS * ZD;
    for (int idx = tid; idx < N_ATOMS * ZD; idx += 256)
        zs[(idx >> 6) * ZP + (idx & 63)] = zm[idx];

    int i1, j1, i2 = 0, j2 = 0;
    { int i = 0, rem = tid;       while (rem >= 31 - i) { rem -= 31 - i; i++; } i1 = i; j1 = i + 1 + rem; }
    const bool has2 = (tid + 256) < EPM;
    if (has2) { int i = 0, rem = tid + 256; while (rem >= 31 - i) { rem -= 31 - i; i++; } i2 = i; j2 = i + 1 + rem; }

    const int c  = tid & 63;
    const int ib = tid >> 6;
    float l1[NBT], l2[NBT];

    __syncthreads();

    #pragma unroll
    for (int t = 0; t < NBT; t++) {
        // W_sym column c -> registers (contiguous row c, by symmetry)
        float w[ZD];
        const float4* Wr = (const float4*)(g_Ws + t * ZD * ZD + c * ZD);
        #pragma unroll
        for (int d4 = 0; d4 < 16; d4++) {
            float4 v = Wr[d4];
            w[4*d4+0] = v.x; w[4*d4+1] = v.y; w[4*d4+2] = v.z; w[4*d4+3] = v.w;
        }
        // U = Z @ W_sym : each thread computes 8 rows of its column c
        #pragma unroll
        for (int p = 0; p < 8; p++) {
            const int i = ib * 8 + p;       // warp-uniform -> smem broadcast
            float a0 = 0.f, a1 = 0.f;
            const float4* zr = (const float4*)(zs + i * ZP);
            #pragma unroll
            for (int d4 = 0; d4 < 16; d4 += 2) {
                float4 v0 = zr[d4], v1 = zr[d4 + 1];
                a0 += v0.x * w[4*d4+0] + v0.y * w[4*d4+1] + v0.z * w[4*d4+2] + v0.w * w[4*d4+3];
                a1 += v1.x * w[4*d4+4] + v1.y * w[4*d4+5] + v1.z * w[4*d4+6] + v1.w * w[4*d4+7];
            }
            us[i * ZP + c] = a0 + a1;
        }
        __syncthreads();

        // logit(e) = U[i] . Z[j]
        {
            const float4* u = (const float4*)(us + i1 * ZP);
            const float4* v = (const float4*)(zs + j1 * ZP);
            float a0 = 0.f, a1 = 0.f;
            #pragma unroll
            for (int d4 = 0; d4 < 16; d4 += 2) {
                float4 uu0 = u[d4], vv0 = v[d4];
                float4 uu1 = u[d4+1], vv1 = v[d4+1];
                a0 += uu0.x*vv0.x + uu0.y*vv0.y + uu0.z*vv0.z + uu0.w*vv0.w;
                a1 += uu1.x*vv1.x + uu1.y*vv1.y + uu1.z*vv1.z + uu1.w*vv1.w;
            }
            l1[t] = a0 + a1;
        }
        if (has2) {
            const float4* u = (const float4*)(us + i2 * ZP);
            const float4* v = (const float4*)(zs + j2 * ZP);
            float a0 = 0.f, a1 = 0.f;
            #pragma unroll
            for (int d4 = 0; d4 < 16; d4 += 2) {
                float4 uu0 = u[d4], vv0 = v[d4];
                float4 uu1 = u[d4+1], vv1 = v[d4+1];
                a0 += uu0.x*vv0.x + uu0.y*vv0.y + uu0.z*vv0.z + uu0.w*vv0.w;
                a1 += uu1.x*vv1.x + uu1.y*vv1.y + uu1.z*vv1.z + uu1.w*vv1.w;
            }
            l2[t] = a0 + a1;
        }
        if (t < NBT - 1) __syncthreads();
    }

    // fused softmax over the 5 types, write final probabilities
    float* eout = out + (size_t)TOTAL_ATOMS * NAT;
    {
        const size_t base = ((size_t)mol * EPM + tid) * NBT;
        float m = fmaxf(fmaxf(fmaxf(l1[0], l1[1]), fmaxf(l1[2], l1[3])), l1[4]);
        float e0 = __expf(l1[0]-m), e1 = __expf(l1[1]-m), e2 = __expf(l1[2]-m),
              e3 = __expf(l1[3]-m), e4 = __expf(l1[4]-m);
        float inv = 1.0f / (e0 + e1 + e2 + e3 + e4);
        eout[base+0] = e0*inv; eout[base+1] = e1*inv; eout[base+2] = e2*inv;
        eout[base+3] = e3*inv; eout[base+4] = e4*inv;
    }
    if (has2) {
        const size_t base = ((size_t)mol * EPM + tid + 256) * NBT;
        float m = fmaxf(fmaxf(fmaxf(l2[0], l2[1]), fmaxf(l2[2], l2[3])), l2[4]);
        float e0 = __expf(l2[0]-m), e1 = __expf(l2[1]-m), e2 = __expf(l2[2]-m),
              e3 = __expf(l2[3]-m), e4 = __expf(l2[4]-m);
        float inv = 1.0f / (e0 + e1 + e2 + e3 + e4);
        eout[base+0] = e0*inv; eout[base+1] = e1*inv; eout[base+2] = e2*inv;
        eout[base+3] = e3*inv; eout[base+4] = e4*inv;
    }
}

// ---------------- launch ----------------------------------------------------
extern "C" void kernel_launch(void* const* d_in, const int* in_sizes, int n_in,
                              void* d_out, int out_size) {
    const float* z     = (const float*)d_in[0];
    const float* W1    = (const float*)d_in[1];
    const float* b1    = (const float*)d_in[2];
    const float* gamma = (const float*)d_in[3];
    const float* beta  = (const float*)d_in[4];
    const float* W2    = (const float*)d_in[5];
    const float* b2    = (const float*)d_in[6];
    const float* bond  = (const float*)d_in[7];
    float* out = (float*)d_out;

    gemm1_kernel <<<NBLK_G1, 256>>>(z, W1, b1);
    sym_kernel   <<<(NBT * ZD * ZD + 255) / 256, 256>>>(bond);
    bnfin_kernel <<<HID, 256>>>(gamma, beta);
    atom_kernel  <<<ATOM_BLKS, 256>>>(W2, b2, out);
    edge_kernel  <<<NUM_MOLS, 256>>>(z, out);
}